// round 1
// baseline (speedup 1.0000x reference)
#include <cuda_runtime.h>
#include <math.h>

// ---------------------------------------------------------------------------
// BDH model forward:  B=2, T=256, D=256, H=4, n=8192, N=32768, V=32000, L=6
// ---------------------------------------------------------------------------
#define Bsz 2
#define Tsz 256
#define Dsz 256
#define Hsz 4
#define nsz 8192
#define Nsz 32768
#define Vsz 32000
#define LAYERS 6
#define LN_EPS 1e-5f
#define SCALE_ATTN 0.011048543456039806f   // 1/sqrt(8192)

// ------------------------- scratch (device globals) ------------------------
__device__ float g_v[Bsz*Tsz*Dsz];                     // 512 KB
__device__ float g_x[(size_t)Bsz*Hsz*Tsz*nsz];         // 64 MB  (x, pre-rope)
__device__ float g_y[(size_t)Bsz*Hsz*Tsz*nsz];         // 64 MB  (xr, later y)
__device__ float g_cos[Tsz*(nsz/2)];                   // 4 MB
__device__ float g_sin[Tsz*(nsz/2)];                   // 4 MB
__device__ float g_sparts[4*Bsz*Hsz*Tsz*Tsz];          // 8 MB   (score split-K partials)
__device__ float g_P[Bsz*Tsz*Tsz];                     // 512 KB (mean attn probs)
__device__ float g_a[Bsz*Tsz*Dsz];                     // 512 KB
__device__ float g_lna[Bsz*Tsz*Dsz];                   // 512 KB
__device__ float g_kparts[16*Bsz*Tsz*Dsz];             // 8 MB   (encoder split-K partials)
__device__ float g_z[Bsz*Tsz*Dsz];                     // 512 KB

// ------------------------- block reductions (256 thr) ----------------------
__device__ __forceinline__ float blk_sum256(float v, float* sh) {
#pragma unroll
    for (int o = 16; o > 0; o >>= 1) v += __shfl_xor_sync(0xffffffffu, v, o);
    if ((threadIdx.x & 31) == 0) sh[threadIdx.x >> 5] = v;
    __syncthreads();
    float tot = 0.f;
#pragma unroll
    for (int w = 0; w < 8; w++) tot += sh[w];
    __syncthreads();
    return tot;
}
__device__ __forceinline__ float blk_max256(float v, float* sh) {
#pragma unroll
    for (int o = 16; o > 0; o >>= 1) v = fmaxf(v, __shfl_xor_sync(0xffffffffu, v, o));
    if ((threadIdx.x & 31) == 0) sh[threadIdx.x >> 5] = v;
    __syncthreads();
    float tot = -3.0e38f;
#pragma unroll
    for (int w = 0; w < 8; w++) tot = fmaxf(tot, sh[w]);
    __syncthreads();
    return tot;
}
// LayerNorm (no affine) over a 256-wide row; one thread per element.
__device__ __forceinline__ float ln_elem(float x, float* sh) {
    float mean = blk_sum256(x, sh) * (1.f / 256.f);
    float d = x - mean;
    float var = blk_sum256(d * d, sh) * (1.f / 256.f);
    return d * rsqrtf(var + LN_EPS);
}

// ------------------------- SGEMM tile machinery ----------------------------
// 64x64 C-tile, BK=16, 256 threads, 4x4 per-thread micro-tile.
__device__ __forceinline__ void load_tile_T(float dst[16][68],
                                            const float* __restrict__ src,
                                            int lda, int tid) {
    // source: K-contiguous rows (row m, stride lda); writes dst[k][m]
    int m  = tid >> 2;
    int ks = (tid & 3) << 2;
    float4 v = *reinterpret_cast<const float4*>(src + (size_t)m * lda + ks);
    dst[ks + 0][m] = v.x; dst[ks + 1][m] = v.y;
    dst[ks + 2][m] = v.z; dst[ks + 3][m] = v.w;
}
__device__ __forceinline__ void load_tile_N(float dst[16][68],
                                            const float* __restrict__ src,
                                            int ldb, int tid) {
    // source: j-contiguous rows (row k, stride ldb); writes dst[k][j]
    int j  = tid & 63;
    int k0 = (tid >> 6) << 2;
#pragma unroll
    for (int u = 0; u < 4; u++) dst[k0 + u][j] = src[(size_t)(k0 + u) * ldb + j];
}
__device__ __forceinline__ void mm_tile(const float As[16][68], const float Bs[16][68],
                                        float acc[4][4], int ty, int tx) {
#pragma unroll
    for (int k = 0; k < 16; k++) {
        float4 a = *reinterpret_cast<const float4*>(&As[k][ty << 2]);
        float4 b = *reinterpret_cast<const float4*>(&Bs[k][tx << 2]);
        float av[4] = {a.x, a.y, a.z, a.w};
        float bv[4] = {b.x, b.y, b.z, b.w};
#pragma unroll
        for (int r = 0; r < 4; r++)
#pragma unroll
            for (int c = 0; c < 4; c++) acc[r][c] = fmaf(av[r], bv[c], acc[r][c]);
    }
}

// ------------------------- kernels -----------------------------------------
__global__ void k_rope_table() {
    int idx = blockIdx.x * 256 + threadIdx.x;     // 256*4096 entries, idx = t*4096+i
    int i = idx & 4095;
    int t = idx >> 12;
    float ex = (float)(2 * i) * (1.0f / 8192.0f);
    float inv = expf(-9.210340371976184f * ex);   // 10000^{-2i/d}
    float f = (float)t * inv;
    float s, c;
    sincosf(f, &s, &c);
    g_cos[idx] = c;
    g_sin[idx] = s;
}

__global__ void k_embed(const int* __restrict__ idx, const float* __restrict__ wte) {
    __shared__ float sh[8];
    int row = blockIdx.x, tid = threadIdx.x;
    int tok = idx[row];
    float x = wte[(size_t)tok * 256 + tid];
    g_v[row * 256 + tid] = ln_elem(x, sh);
}

// x = relu(v @ decoder) [mode 0 -> g_x], or y = relu(lna @ decoder) * x [mode 1 -> g_y]
__global__ void __launch_bounds__(256) k_gemm_dec(const float* __restrict__ W, int mode) {
    __shared__ float As[16][68], Bs[16][68];
    const float* A = mode ? g_lna : g_v;
    float* out = mode ? g_y : g_x;
    int tid = threadIdx.x, tx = tid & 15, ty = tid >> 4;
    int col0 = blockIdx.x << 6;         // 0..32767 (global column = h*n+i)
    int row0 = blockIdx.y << 6;         // 0..511
    int h  = col0 >> 13;
    int i0 = col0 & 8191;
    const float* Wh = W + (size_t)h * 256 * 8192 + i0;  // element (d,i) at Wh[d*8192+i]
    float acc[4][4] = {};
    for (int kk = 0; kk < 256; kk += 16) {
        load_tile_T(As, A + (size_t)row0 * 256 + kk, 256, tid);
        load_tile_N(Bs, Wh + (size_t)kk * 8192, 8192, tid);
        __syncthreads();
        mm_tile(As, Bs, acc, ty, tx);
        __syncthreads();
    }
    int b  = row0 >> 8;
    int t0 = (row0 & 255) + (ty << 2);
#pragma unroll
    for (int r = 0; r < 4; r++) {
        int t = t0 + r;
        size_t ob = (((size_t)(b * 4 + h) * 256 + t) * 8192) + i0 + (tx << 2);
#pragma unroll
        for (int c = 0; c < 4; c++) {
            float vl = fmaxf(acc[r][c], 0.f);
            if (mode) vl *= g_x[ob + c];
            out[ob + c] = vl;
        }
    }
}

__global__ void k_rope() {
    int idx = blockIdx.x * 256 + threadIdx.x;   // 2*4*256*4096 pairs
    int i = idx & 4095;
    int t = (idx >> 12) & 255;
    int bh = idx >> 20;
    size_t base = ((size_t)(bh * 256 + t)) * 8192 + 2 * i;
    int ti = idx & 0xFFFFF;                      // t*4096 + i
    float c = g_cos[ti], s = g_sin[ti];
    float xe = g_x[base], xo = g_x[base + 1];
    g_y[base]     = xe * c - xo * s;
    g_y[base + 1] = xo * c + xe * s;
}

// S = Xr Xr^T, lower-triangle tiles only, split-K over 4 chunks of 2048
__global__ void __launch_bounds__(256) k_scores() {
    __shared__ float As[16][68], Bs[16][68];
    const int TR[10] = {0,1,1,2,2,2,3,3,3,3};
    const int TC[10] = {0,0,1,0,1,2,0,1,2,3};
    int tid = threadIdx.x, tx = tid & 15, ty = tid >> 4;
    int row0 = TR[blockIdx.x] << 6;
    int col0 = TC[blockIdx.x] << 6;
    int bh = blockIdx.y;
    int sp = blockIdx.z;
    const float* X = g_y + (size_t)bh * 256 * 8192;
    float acc[4][4] = {};
    int k0 = sp * 2048;
    for (int kk = k0; kk < k0 + 2048; kk += 16) {
        load_tile_T(As, X + (size_t)row0 * 8192 + kk, 8192, tid);
        load_tile_T(Bs, X + (size_t)col0 * 8192 + kk, 8192, tid);
        __syncthreads();
        mm_tile(As, Bs, acc, ty, tx);
        __syncthreads();
    }
#pragma unroll
    for (int r = 0; r < 4; r++) {
        int t = row0 + (ty << 2) + r;
        size_t ob = (((size_t)sp * 8 + bh) * 256 + t) * 256 + col0 + (tx << 2);
#pragma unroll
        for (int c = 0; c < 4; c++) g_sparts[ob + c] = acc[r][c];
    }
}

// per (b,t) row: combine splits, causal mask, per-head softmax, mean over heads
__global__ void k_softmax() {
    __shared__ float sh[8];
    int row = blockIdx.x;        // b*256+t
    int b = row >> 8, t = row & 255;
    int s = threadIdx.x;
    float pacc = 0.f;
    for (int h = 0; h < 4; h++) {
        float val = -3.0e38f;
        if (s <= t) {
            float sum = 0.f;
            int bh = b * 4 + h;
#pragma unroll
            for (int sp = 0; sp < 4; sp++)
                sum += g_sparts[(((size_t)sp * 8 + bh) * 256 + t) * 256 + s];
            val = sum * SCALE_ATTN;
        }
        float mx = blk_max256(val, sh);
        float e = (s <= t) ? expf(val - mx) : 0.f;
        float ssum = blk_sum256(e, sh);
        pacc += e / ssum;
    }
    g_P[(size_t)row * 256 + s] = pacc * 0.25f;
}

// a = P @ v  (per-batch 256x256x256)
__global__ void __launch_bounds__(256) k_pv() {
    __shared__ float As[16][68], Bs[16][68];
    int tid = threadIdx.x, tx = tid & 15, ty = tid >> 4;
    int col0 = blockIdx.x << 6, row0 = blockIdx.y << 6, b = blockIdx.z;
    const float* A  = g_P + (size_t)b * 65536;
    const float* Bv = g_v + (size_t)b * 65536;
    float acc[4][4] = {};
    for (int kk = 0; kk < 256; kk += 16) {
        load_tile_T(As, A + (size_t)row0 * 256 + kk, 256, tid);
        load_tile_N(Bs, Bv + (size_t)kk * 256 + col0, 256, tid);
        __syncthreads();
        mm_tile(As, Bs, acc, ty, tx);
        __syncthreads();
    }
#pragma unroll
    for (int r = 0; r < 4; r++) {
        size_t ob = ((size_t)b * 256 + row0 + (ty << 2) + r) * 256 + col0 + (tx << 2);
#pragma unroll
        for (int c = 0; c < 4; c++) g_a[ob + c] = acc[r][c];
    }
}

__global__ void k_ln_a() {
    __shared__ float sh[8];
    int row = blockIdx.x, tid = threadIdx.x;
    float x = g_a[row * 256 + tid];
    g_lna[row * 256 + tid] = ln_elem(x, sh);
}

// z_partials = y_flat @ encoder  (K=32768, split into 16 chunks of 2048)
__global__ void __launch_bounds__(256) k_enc(const float* __restrict__ E) {
    __shared__ float As[16][68], Bs[16][68];
    int tid = threadIdx.x, tx = tid & 15, ty = tid >> 4;
    int col0 = blockIdx.x << 6, row0 = blockIdx.y << 6, sp = blockIdx.z;
    int b = row0 >> 8, t0 = row0 & 255;
    int k0 = sp * 2048;
    int h = k0 >> 13, i0 = k0 & 8191;   // split never straddles a head
    const float* Ab = g_y + (((size_t)(b * 4 + h) * 256 + t0) * 8192) + i0;
    float acc[4][4] = {};
    for (int kk = 0; kk < 2048; kk += 16) {
        load_tile_T(As, Ab + kk, 8192, tid);
        load_tile_N(Bs, E + (size_t)(k0 + kk) * 256 + col0, 256, tid);
        __syncthreads();
        mm_tile(As, Bs, acc, ty, tx);
        __syncthreads();
    }
#pragma unroll
    for (int r = 0; r < 4; r++) {
        size_t ob = ((size_t)sp * 512 + row0 + (ty << 2) + r) * 256 + col0 + (tx << 2);
#pragma unroll
        for (int c = 0; c < 4; c++) g_kparts[ob + c] = acc[r][c];
    }
}

__global__ void k_reduce() {
    int i = blockIdx.x * 256 + threadIdx.x;   // 131072 elements
    float s = 0.f;
#pragma unroll
    for (int sp = 0; sp < 16; sp++) s += g_kparts[(size_t)sp * 131072 + i];
    g_z[i] = s;
}

// v = ln(v + ln(z))
__global__ void k_residual() {
    __shared__ float sh[8];
    int row = blockIdx.x, tid = threadIdx.x;
    float z = g_z[row * 256 + tid];
    float lnz = ln_elem(z, sh);
    float t = g_v[row * 256 + tid] + lnz;
    g_v[row * 256 + tid] = ln_elem(t, sh);
}

__global__ void __launch_bounds__(256) k_readout(const float* __restrict__ R,
                                                 float* __restrict__ out) {
    __shared__ float As[16][68], Bs[16][68];
    int tid = threadIdx.x, tx = tid & 15, ty = tid >> 4;
    int col0 = blockIdx.x << 6, row0 = blockIdx.y << 6;
    float acc[4][4] = {};
    for (int kk = 0; kk < 256; kk += 16) {
        load_tile_T(As, g_v + (size_t)row0 * 256 + kk, 256, tid);
        load_tile_N(Bs, R + (size_t)kk * 32000 + col0, 32000, tid);
        __syncthreads();
        mm_tile(As, Bs, acc, ty, tx);
        __syncthreads();
    }
#pragma unroll
    for (int r = 0; r < 4; r++) {
        size_t ob = (size_t)(row0 + (ty << 2) + r) * 32000 + col0 + (tx << 2);
#pragma unroll
        for (int c = 0; c < 4; c++) out[ob + c] = acc[r][c];
    }
}

// ------------------------- host launcher -----------------------------------
extern "C" void kernel_launch(void* const* d_in, const int* in_sizes, int n_in,
                              void* d_out, int out_size) {
    const int*   idx  = (const int*)d_in[0];
    const float* wte  = (const float*)d_in[1];
    const float* enc  = (const float*)d_in[2];
    const float* decx = (const float*)d_in[3];
    const float* decy = (const float*)d_in[4];
    const float* ro   = (const float*)d_in[5];
    float* out = (float*)d_out;
    (void)in_sizes; (void)n_in; (void)out_size;

    k_rope_table<<<4096, 256>>>();
    k_embed<<<512, 256>>>(idx, wte);

    for (int l = 0; l < LAYERS; l++) {
        k_gemm_dec<<<dim3(512, 8), 256>>>(decx, 0);   // x = relu(v @ Wx)
        k_rope<<<32768, 256>>>();                     // xr = rope(x) -> g_y
        k_scores<<<dim3(10, 8, 4), 256>>>();          // S partials (causal tiles)
        k_softmax<<<512, 256>>>();                    // P = mean_h softmax(S)
        k_pv<<<dim3(4, 4, 2), 256>>>();               // a = P @ v
        k_ln_a<<<512, 256>>>();                       // lna = ln(a)
        k_gemm_dec<<<dim3(512, 8), 256>>>(decy, 1);   // y = relu(lna @ Wy) * x -> g_y
        k_enc<<<dim3(4, 8, 16), 256>>>(enc);          // z partials = y_flat @ E
        k_reduce<<<512, 256>>>();                     // z
        k_residual<<<512, 256>>>();                   // v = ln(v + ln(z))
    }

    k_readout<<<dim3(500, 8), 256>>>(ro, out);        // out = v @ readout
}